// round 15
// baseline (speedup 1.0000x reference)
#include <cuda_runtime.h>
#include <stdint.h>
#include <math.h>

#define HH 1280
#define WW 1920
#define BB 2
#define OH 427
#define OW 640
#define SENT2 0x7FFF7FFFu   // sentinel coords (32767,32767): loses to every real seed
#define RPB 9               // rows owned per block
#define GROWS (BB * HH)     // 2560
#define NBLKS ((GROWS + RPB - 1) / RPB)   // 285 <= 296 co-resident slots

// Scratch (device globals: allocation-free rule)
__device__ float    g_depth[BB][HH * WW];          // 19.6 MB
__device__ uint32_t g_near[2][BB][HH * WW];        // 2 x 19.6 MB, ping-pong
__device__ float    g_full[BB][2][HH * WW];        // filled + dist, 39.3 MB

// software grid barrier state (count returns to 0 after each barrier; gen monotonic)
__device__ unsigned g_cnt;
__device__ unsigned g_gen;

__device__ const int c_steps[12] = {1, 1024, 512, 256, 128, 64, 32, 16, 8, 4, 2, 1};

// ---------------------------------------------------------------------------
// XLA fused-emitter dot: separate multiplies, k-ascending adds, NO fma.
__device__ __forceinline__ float dot3_nofma(float a0, float a1, float a2,
                                            float b0, float b1, float b2) {
    float p0 = __fmul_rn(a0, b0);
    float p1 = __fmul_rn(a1, b1);
    float p2 = __fmul_rn(a2, b2);
    return __fadd_rn(__fadd_rn(p0, p1), p2);
}

// winner select, branch-free: packed |dr|,|dc| via vabsdiff2, exact int dist.
__device__ __forceinline__ uint32_t jfa_better(uint32_t cur, uint32_t cand, uint32_t ij) {
    unsigned a = __vabsdiffs2(ij, cur);
    unsigned b = __vabsdiffs2(ij, cand);
    unsigned da = (a >> 16) * (a >> 16) + (a & 0xFFFFu) * (a & 0xFFFFu);
    unsigned db = (b >> 16) * (b >> 16) + (b & 0xFFFFu) * (b & 0xFFFFu);
    return (db < da) ? cand : cur;
}

__device__ __forceinline__ uint32_t seedv(int r, int c, float d) {
    return (d != 0.f) ? (uint32_t)((r << 16) | c) : SENT2;
}

// grid barrier: release = threadfence'd writes + gen bump; acquire = volatile
// poll + threadfence. All neighbor data reads use __ldcg (L2) — L1 is not
// coherent across blocks within one kernel.
__device__ __forceinline__ void gbar(unsigned& myGen) {
    __threadfence();
    __syncthreads();
    if (threadIdx.x == 0) {
        unsigned arr = atomicAdd(&g_cnt, 1u);
        if (arr == (unsigned)(NBLKS - 1)) {
            atomicExch(&g_cnt, 0u);
            __threadfence();
            atomicAdd(&g_gen, 1u);
        } else {
            while (*((volatile unsigned*)&g_gen) - myGen < 1u) { }
            __threadfence();
        }
    }
    __syncthreads();
    myGen += 1u;
}

// ---------------------------------------------------------------------------
// 1) zero depth canvas
__global__ void zero_depth_kernel(int nb) {
    int t = blockIdx.x * blockDim.x + threadIdx.x;
    int total = nb * HH * WW / 4;
    if (t < total) reinterpret_cast<float4*>(g_depth)[t] = make_float4(0.f, 0.f, 0.f, 0.f);
}

// ---------------------------------------------------------------------------
// 2) project points, scatter-add depth (duplicates sum, like reference)
__global__ void scatter_kernel(const float* __restrict__ pts,
                               const float* __restrict__ pose,
                               const float* __restrict__ ext,
                               const float* __restrict__ intr,
                               int N) {
    int idx = blockIdx.x * blockDim.x + threadIdx.x;
    int b = blockIdx.y;
    if (idx >= N) return;
    const float* p = pts + ((size_t)b * N + idx) * 3;
    float x = p[0], y = p[1], z = p[2];
    const float* P = pose + b * 16;
    const float* E = ext + b * 16;
    const float* K = intr + b * 9;
    float wx = __fadd_rn(dot3_nofma(x, y, z, P[0], P[1], P[2]),  P[3]);
    float wy = __fadd_rn(dot3_nofma(x, y, z, P[4], P[5], P[6]),  P[7]);
    float wz = __fadd_rn(dot3_nofma(x, y, z, P[8], P[9], P[10]), P[11]);
    float cx = __fadd_rn(dot3_nofma(wx, wy, wz, E[0], E[1], E[2]),  E[3]);
    float cy = __fadd_rn(dot3_nofma(wx, wy, wz, E[4], E[5], E[6]),  E[7]);
    float cz = __fadd_rn(dot3_nofma(wx, wy, wz, E[8], E[9], E[10]), E[11]);
    float pu = dot3_nofma(cx, cy, cz, K[0], K[1], K[2]);
    float pv = dot3_nofma(cx, cy, cz, K[3], K[4], K[5]);
    float pw = dot3_nofma(cx, cy, cz, K[6], K[7], K[8]);
    float u = __fdiv_rn(pu, pw);
    float v = __fdiv_rn(pv, pw);
    int r = (int)floorf(v);
    int c = (int)floorf(u);
    if (r >= 0 && r < HH && c >= 0 && c < WW) {
        float x2 = __fmul_rn(x, x);
        float y2 = __fmul_rn(y, y);
        float z2 = __fmul_rn(z, z);
        float d = __fsqrt_rn(__fadd_rn(__fadd_rn(x2, y2), z2));
        atomicAdd(&g_depth[b][r * WW + c], d);
    }
}

// ---------------------------------------------------------------------------
// 3) persistent JFA: all 12 steps x 8 directions in ONE kernel.
//    Each block owns RPB rows; cur state lives in registers; gmem traffic per
//    direction = 1 neighbor read (.cg) + 1 write. Jacobi ping-pong preserved
//    exactly (read bufS, write bufD); D,E pair is row-local via smem.
__global__ void __launch_bounds__(480, 2) jfa_persist_kernel() {
    __shared__ uint32_t rowbuf[WW];
    const int j0 = threadIdx.x * 4;
    unsigned myGen = *((volatile unsigned*)&g_gen);
    const int g0 = blockIdx.x * RPB;

    uint32_t cur[RPB][4];

    // ---- init seeds from depth -> regs + g_near[0] ----
#pragma unroll
    for (int r = 0; r < RPB; r++) {
        int g = g0 + r;
        if (g < GROWS) {
            int b = g / HH;
            int i = g - b * HH;
            const float* dp = g_depth[b] + (size_t)i * WW + j0;
            float4 d0 = *reinterpret_cast<const float4*>(dp);
            cur[r][0] = seedv(i, j0 + 0, d0.x);
            cur[r][1] = seedv(i, j0 + 1, d0.y);
            cur[r][2] = seedv(i, j0 + 2, d0.z);
            cur[r][3] = seedv(i, j0 + 3, d0.w);
            *reinterpret_cast<uint4*>(g_near[0][b] + (size_t)i * WW + j0) =
                make_uint4(cur[r][0], cur[r][1], cur[r][2], cur[r][3]);
        } else {
            cur[r][0] = cur[r][1] = cur[r][2] = cur[r][3] = SENT2;
        }
    }
    gbar(myGen);
    int src = 0;

    // one gmem direction: cand(i,j) = bufS(i-dy, j-dx); write post to bufD.
    auto jdir = [&](int dy, int dx) {
#pragma unroll
        for (int r = 0; r < RPB; r++) {
            int g = g0 + r;
            bool okrow = (g < GROWS);
            int b = okrow ? (g / HH) : 0;
            int i = g - b * HH;
            const uint32_t* S = g_near[src][b];
            uint32_t* D = g_near[src ^ 1][b];
            const int si = i - dy;
            const int jb = j0 - dx;
            uint32_t cand[4];
            bool okn = okrow & ((unsigned)si < (unsigned)HH);
            if (okn && ((dx & 3) == 0)) {
                if ((unsigned)jb < (unsigned)WW) {      // quad all-or-none
                    uint4 n = __ldcg(reinterpret_cast<const uint4*>(S + (size_t)si * WW + jb));
                    cand[0] = n.x; cand[1] = n.y; cand[2] = n.z; cand[3] = n.w;
                } else {
                    cand[0] = cand[1] = cand[2] = cand[3] = SENT2;
                }
            } else if (okn) {
#pragma unroll
                for (int t = 0; t < 4; t++) {
                    int sj = jb + t;
                    cand[t] = ((unsigned)sj < (unsigned)WW)
                              ? __ldcg(S + (size_t)si * WW + sj) : SENT2;
                }
            } else {
                cand[0] = cand[1] = cand[2] = cand[3] = SENT2;
            }
            const uint32_t ij = ((uint32_t)i << 16) | (uint32_t)j0;
#pragma unroll
            for (int t = 0; t < 4; t++) cur[r][t] = jfa_better(cur[r][t], cand[t], ij + t);
            if (okrow)
                *reinterpret_cast<uint4*>(D + (size_t)i * WW + j0) =
                    make_uint4(cur[r][0], cur[r][1], cur[r][2], cur[r][3]);
        }
        gbar(myGen);
        src ^= 1;
    };

    // fused D,E: (0,-k) then (0,+k), row-local via smem, post-E -> bufD.
    auto jDE = [&](int k) {
        for (int r = 0; r < RPB; r++) {
            int g = g0 + r;
            bool okrow = (g < GROWS);
            int b = okrow ? (g / HH) : 0;
            int i = g - b * HH;
            const uint32_t ij = ((uint32_t)i << 16) | (uint32_t)j0;
            __syncthreads();                 // rowbuf free from previous row
            if (okrow)
                *reinterpret_cast<uint4*>(rowbuf + j0) =
                    make_uint4(cur[r][0], cur[r][1], cur[r][2], cur[r][3]);
            __syncthreads();
            // D: cand = row[j + k]
            uint32_t nv[4];
            {
                int jb = j0 + k;
                uint32_t cd[4];
                if ((k & 3) == 0 && jb + 3 < WW) {
                    uint4 n = *reinterpret_cast<const uint4*>(rowbuf + jb);
                    cd[0] = n.x; cd[1] = n.y; cd[2] = n.z; cd[3] = n.w;
                } else {
#pragma unroll
                    for (int t = 0; t < 4; t++) cd[t] = (jb + t < WW) ? rowbuf[jb + t] : SENT2;
                }
#pragma unroll
                for (int t = 0; t < 4; t++) nv[t] = jfa_better(cur[r][t], cd[t], ij + t);
            }
            __syncthreads();                 // all D reads done
            if (okrow)
                *reinterpret_cast<uint4*>(rowbuf + j0) = make_uint4(nv[0], nv[1], nv[2], nv[3]);
            __syncthreads();
            // E: cand = row[j - k]
            {
                int jb = j0 - k;
                uint32_t cd[4];
                if ((k & 3) == 0 && jb >= 0) {
                    uint4 n = *reinterpret_cast<const uint4*>(rowbuf + jb);
                    cd[0] = n.x; cd[1] = n.y; cd[2] = n.z; cd[3] = n.w;
                } else {
#pragma unroll
                    for (int t = 0; t < 4; t++) cd[t] = (jb + t >= 0) ? rowbuf[jb + t] : SENT2;
                }
#pragma unroll
                for (int t = 0; t < 4; t++) cur[r][t] = jfa_better(nv[t], cd[t], ij + t);
            }
            if (okrow)
                *reinterpret_cast<uint4*>(g_near[src ^ 1][b] + (size_t)i * WW + j0) =
                    make_uint4(cur[r][0], cur[r][1], cur[r][2], cur[r][3]);
        }
        gbar(myGen);
        src ^= 1;
    };

    // reference order per step: A(-k,-k) B(-k,0) C(-k,k) D(0,-k) E(0,k)
    //                            F(k,-k)  G(k,0)  H(k,k)
    for (int s = 0; s < 12; s++) {
        const int k = c_steps[s];
        jdir(-k, -k);
        jdir(-k,  0);
        jdir(-k,  k);
        jDE(k);
        jdir( k, -k);
        jdir( k,  0);
        jdir( k,  k);
    }
    // 84 phase flips (even) -> final state in g_near[0]
}

// ---------------------------------------------------------------------------
// 4) filled depth + distance map
__global__ void fill_kernel(int nb, int finalSel) {
    int t = blockIdx.x * blockDim.x + threadIdx.x;
    int total = nb * HH * WW;
    if (t >= total) return;
    int b = t / (HH * WW);
    int pix = t % (HH * WW);
    int i = pix / WW;
    int j = pix % WW;
    float dep = g_depth[b][pix];
    uint32_t nn = g_near[finalSel][b][pix];
    int nr = (int)(nn >> 16);     if (nr > HH - 1) nr = HH - 1;
    int nc = (int)(nn & 0xFFFFu); if (nc > WW - 1) nc = WW - 1;
    bool valid = (dep != 0.f);
    float filled = valid ? dep : g_depth[b][nr * WW + nc];
    float dr = __fadd_rn((float)i, -(float)nr);
    float dc = __fadd_rn((float)j, -(float)nc);
    float dist = valid ? 0.f : __fsqrt_rn(__fadd_rn(__fmul_rn(dr, dr), __fmul_rn(dc, dc)));
    g_full[b][0][pix] = filled;
    g_full[b][1][pix] = dist;
}

// ---------------------------------------------------------------------------
// 5) jax.image.resize(method='linear', antialias=True): separable triangle,
//    fp32 weights exactly as jax computes them, fp32 accumulation.
__global__ void resize_kernel(float* __restrict__ out, int nb) {
    int t = blockIdx.x * blockDim.x + threadIdx.x;
    int total = nb * 2 * OH * OW;
    if (t >= total) return;
    int ox = t % OW;
    int oy = (t / OW) % OH;
    int ch = (t / (OW * OH)) % 2;
    int b  =  t / (OW * OH * 2);

    const double s_h = (double)OH / (double)HH;
    const double s_w = (double)OW / (double)WW;
    const float inv_h = (float)(1.0 / s_h);
    const float inv_w = (float)(1.0 / s_w);

    float sfy = __fadd_rn(__fmul_rn(__fadd_rn((float)oy, 0.5f), inv_h), -0.5f);
    float sfx = __fadd_rn(__fmul_rn(__fadd_rn((float)ox, 0.5f), inv_w), -0.5f);

    int y0 = (int)ceilf(sfy - inv_h) - 1;  if (y0 < 0) y0 = 0;
    int y1 = (int)floorf(sfy + inv_h) + 1; if (y1 > HH - 1) y1 = HH - 1;
    int x0 = (int)ceilf(sfx - inv_w) - 1;  if (x0 < 0) x0 = 0;
    int x1 = (int)floorf(sfx + inv_w) + 1; if (x1 > WW - 1) x1 = WW - 1;

    float wx[10];
    float wxs = 0.0f;
    int nx = x1 - x0 + 1;
    if (nx > 10) nx = 10;
    for (int k = 0; k < nx; k++) {
        float d = fabsf(__fadd_rn(sfx, -(float)(x0 + k)));
        float xx = __fdiv_rn(d, inv_w);
        float w = __fadd_rn(1.0f, -xx);
        if (w < 0.0f) w = 0.0f;
        wx[k] = w;
        wxs = __fadd_rn(wxs, w);
    }
    for (int k = 0; k < nx; k++) wx[k] = __fdiv_rn(wx[k], wxs);

    const float* __restrict__ src = g_full[b][ch];
    float acc = 0.0f;
    float wys = 0.0f;
    float wy[10];
    int ny = y1 - y0 + 1;
    if (ny > 10) ny = 10;
    for (int k = 0; k < ny; k++) {
        float d = fabsf(__fadd_rn(sfy, -(float)(y0 + k)));
        float xx = __fdiv_rn(d, inv_h);
        float w = __fadd_rn(1.0f, -xx);
        if (w < 0.0f) w = 0.0f;
        wy[k] = w;
        wys = __fadd_rn(wys, w);
    }
    for (int k = 0; k < ny; k++) {
        float wyn = __fdiv_rn(wy[k], wys);
        const float* row = src + (y0 + k) * WW;
        float rowacc = 0.0f;
        for (int m = 0; m < nx; m++) {
            rowacc = __fmaf_rn(wx[m], row[x0 + m], rowacc);
        }
        acc = __fmaf_rn(wyn, rowacc, acc);
    }
    out[(((size_t)b * 2 + ch) * OH + oy) * OW + ox] = acc;
}

// ---------------------------------------------------------------------------
extern "C" void kernel_launch(void* const* d_in, const int* in_sizes, int n_in,
                              void* d_out, int out_size) {
    const float* pts  = (const float*)d_in[0];  // (B,N,3)
    const float* pose = (const float*)d_in[1];  // (B,4,4)
    const float* ext  = (const float*)d_in[2];  // (B,4,4)
    const float* intr = (const float*)d_in[3];  // (B,3,3)

    int nb = in_sizes[1] / 16;
    if (nb < 1) nb = 1;
    if (nb > BB) nb = BB;
    int N = in_sizes[0] / (nb * 3);

    int totalPix = nb * HH * WW;

    zero_depth_kernel<<<(totalPix / 4 + 255) / 256, 256>>>(nb);

    dim3 sg((N + 255) / 256, nb);
    scatter_kernel<<<sg, 256>>>(pts, pose, ext, intr, N);

    // all 12 JFA steps in one persistent kernel (285 co-resident blocks)
    jfa_persist_kernel<<<NBLKS, 480>>>();

    // 84 phase flips (even): final buffer = 0
    fill_kernel<<<(totalPix + 255) / 256, 256>>>(nb, 0);

    int outTotal = nb * 2 * OH * OW;
    resize_kernel<<<(outTotal + 255) / 256, 256>>>((float*)d_out, nb);
}

// round 16
// speedup vs baseline: 1.6111x; 1.6111x over previous
#include <cuda_runtime.h>
#include <stdint.h>
#include <math.h>

#define HH 1280
#define WW 1920
#define BB 2
#define OH 427
#define OW 640
#define SENT 0xFFFFFFFFu

// Scratch (device globals: allocation-free rule)
__device__ float    g_depth[BB][HH * WW];          // 19.6 MB
__device__ uint32_t g_near[2][BB][HH * WW];        // 2 x 19.6 MB, ping-pong
__device__ float    g_full[BB][2][HH * WW];        // filled + dist, 39.3 MB

// ---------------------------------------------------------------------------
// XLA fused-emitter dot: separate multiplies, k-ascending adds, NO fma.
__device__ __forceinline__ float dot3_nofma(float a0, float a1, float a2,
                                            float b0, float b1, float b2) {
    float p0 = __fmul_rn(a0, b0);
    float p1 = __fmul_rn(a1, b1);
    float p2 = __fmul_rn(a2, b2);
    return __fadd_rn(__fadd_rn(p0, p1), p2);
}

// R5-convention winner select: strict '<', exact int dist, SENT -> INT_MAX.
__device__ __forceinline__ uint32_t jfa_better5(uint32_t c0, uint32_t cand, int i, int j) {
    int db, dc;
    if (c0 == SENT) db = 0x7FFFFFFF;
    else { int a = i - (int)(c0 >> 16); int e = j - (int)(c0 & 0xFFFFu); db = a * a + e * e; }
    if (cand == SENT) dc = 0x7FFFFFFF;
    else { int a = i - (int)(cand >> 16); int e = j - (int)(cand & 0xFFFFu); dc = a * a + e * e; }
    return (dc < db) ? cand : c0;
}

__device__ __forceinline__ uint32_t seedv(int r, int c, float d) {
    return (d != 0.f) ? (uint32_t)((r << 16) | c) : SENT;
}

// ---------------------------------------------------------------------------
// 1) zero depth canvas
__global__ void zero_depth_kernel(int nb) {
    int t = blockIdx.x * blockDim.x + threadIdx.x;
    int total = nb * HH * WW / 4;
    if (t < total) reinterpret_cast<float4*>(g_depth)[t] = make_float4(0.f, 0.f, 0.f, 0.f);
}

// ---------------------------------------------------------------------------
// 2) project points, scatter-add depth (duplicates sum, like reference)
__global__ void scatter_kernel(const float* __restrict__ pts,
                               const float* __restrict__ pose,
                               const float* __restrict__ ext,
                               const float* __restrict__ intr,
                               int N) {
    int idx = blockIdx.x * blockDim.x + threadIdx.x;
    int b = blockIdx.y;
    if (idx >= N) return;
    const float* p = pts + ((size_t)b * N + idx) * 3;
    float x = p[0], y = p[1], z = p[2];
    const float* P = pose + b * 16;
    const float* E = ext + b * 16;
    const float* K = intr + b * 9;
    float wx = __fadd_rn(dot3_nofma(x, y, z, P[0], P[1], P[2]),  P[3]);
    float wy = __fadd_rn(dot3_nofma(x, y, z, P[4], P[5], P[6]),  P[7]);
    float wz = __fadd_rn(dot3_nofma(x, y, z, P[8], P[9], P[10]), P[11]);
    float cx = __fadd_rn(dot3_nofma(wx, wy, wz, E[0], E[1], E[2]),  E[3]);
    float cy = __fadd_rn(dot3_nofma(wx, wy, wz, E[4], E[5], E[6]),  E[7]);
    float cz = __fadd_rn(dot3_nofma(wx, wy, wz, E[8], E[9], E[10]), E[11]);
    float pu = dot3_nofma(cx, cy, cz, K[0], K[1], K[2]);
    float pv = dot3_nofma(cx, cy, cz, K[3], K[4], K[5]);
    float pw = dot3_nofma(cx, cy, cz, K[6], K[7], K[8]);
    float u = __fdiv_rn(pu, pw);
    float v = __fdiv_rn(pv, pw);
    int r = (int)floorf(v);
    int c = (int)floorf(u);
    if (r >= 0 && r < HH && c >= 0 && c < WW) {
        float x2 = __fmul_rn(x, x);
        float y2 = __fmul_rn(y, y);
        float z2 = __fmul_rn(z, z);
        float d = __fsqrt_rn(__fadd_rn(__fadd_rn(x2, y2), z2));
        atomicAdd(&g_depth[b][r * WW + c], d);
    }
}

// ---------------------------------------------------------------------------
// 3) first JFA op: fused seed-init + directions A=(-1,-1), B=(-1,0) of the
//    k=1 step. Seeds formed inline from depth (replaces init_near kernel).
//    Exact sequential recomputation:
//      postA(i,j) = better(seed(i,j), seed(i+1, j+1))
//      candB(i,j) = postA(i+1, j) = better_{(i+1,j)}(seed(i+1,j), seed(i+2,j+1))
//      out(i,j)   = better(postA(i,j), candB(i,j))
__global__ void __launch_bounds__(480) jfa_pair_init(int nb) {
    const int b = blockIdx.z;
    const int i = blockIdx.y;
    const int j0 = threadIdx.x * 4;
    const float* __restrict__ dp = g_depth[b];
    uint32_t* __restrict__ dst = g_near[0][b];

    const int r1 = i + 1, r2 = i + 2;
    const bool ok1 = (r1 < HH);
    const bool ok2 = (r2 < HH);
    const bool okr = (j0 + 7 < WW);

    float4 dC = *reinterpret_cast<const float4*>(dp + i * WW + j0);
    uint32_t curv[4] = { seedv(i, j0 + 0, dC.x), seedv(i, j0 + 1, dC.y),
                         seedv(i, j0 + 2, dC.z), seedv(i, j0 + 3, dC.w) };

    uint32_t w1[8], w2[8];
#pragma unroll
    for (int t = 0; t < 8; t++) { w1[t] = SENT; w2[t] = SENT; }
    if (ok1) {
        float4 a = __ldg(reinterpret_cast<const float4*>(dp + r1 * WW + j0));
        w1[0] = seedv(r1, j0 + 0, a.x); w1[1] = seedv(r1, j0 + 1, a.y);
        w1[2] = seedv(r1, j0 + 2, a.z); w1[3] = seedv(r1, j0 + 3, a.w);
        if (okr) {
            float4 c = __ldg(reinterpret_cast<const float4*>(dp + r1 * WW + j0 + 4));
            w1[4] = seedv(r1, j0 + 4, c.x); w1[5] = seedv(r1, j0 + 5, c.y);
            w1[6] = seedv(r1, j0 + 6, c.z); w1[7] = seedv(r1, j0 + 7, c.w);
        }
    }
    if (ok2) {
        float4 a = __ldg(reinterpret_cast<const float4*>(dp + r2 * WW + j0));
        w2[0] = seedv(r2, j0 + 0, a.x); w2[1] = seedv(r2, j0 + 1, a.y);
        w2[2] = seedv(r2, j0 + 2, a.z); w2[3] = seedv(r2, j0 + 3, a.w);
        if (okr) {
            float4 c = __ldg(reinterpret_cast<const float4*>(dp + r2 * WW + j0 + 4));
            w2[4] = seedv(r2, j0 + 4, c.x); w2[5] = seedv(r2, j0 + 5, c.y);
            w2[6] = seedv(r2, j0 + 6, c.z); w2[7] = seedv(r2, j0 + 7, c.w);
        }
    }

    uint32_t outv[4];
#pragma unroll
    for (int t = 0; t < 4; t++) {
        int j = j0 + t;
        uint32_t a1 = jfa_better5(curv[t], w1[t + 1], i, j);    // post-A
        uint32_t a2 = jfa_better5(w1[t], w2[t + 1], r1, j);     // candB
        outv[t] = jfa_better5(a1, a2, i, j);                    // post-B
    }
    *reinterpret_cast<uint4*>(dst + i * WW + j0) = make_uint4(outv[0], outv[1], outv[2], outv[3]);
}

// ---------------------------------------------------------------------------
// 4) one JFA direction pass (R5 champion body, byte-identical).
//    Vectorized neighbor fetch: dx%4==0 -> single aligned uint4;
//    else two aligned uint4 + select; edges fall back to scalar.
__global__ void __launch_bounds__(480) jfa_pass_kernel(int srcSel, int dy, int dx) {
    const int b = blockIdx.z;
    const int i = blockIdx.y;
    const int j0 = threadIdx.x * 4;
    const uint32_t* __restrict__ s = g_near[srcSel][b];
    uint32_t* __restrict__ dpt = g_near[srcSel ^ 1][b];
    uint4 cur = *reinterpret_cast<const uint4*>(s + i * WW + j0);
    const int si = i - dy;
    const bool rowok = ((unsigned)si < (unsigned)HH);
    uint32_t candv[4];
    const int jb = j0 - dx;                       // first source column
    if (!rowok) {
        candv[0] = candv[1] = candv[2] = candv[3] = SENT;
    } else if ((dx & 3) == 0) {
        if (jb >= 0 && jb + 3 < WW) {
            uint4 n = __ldg(reinterpret_cast<const uint4*>(s + si * WW + jb));
            candv[0] = n.x; candv[1] = n.y; candv[2] = n.z; candv[3] = n.w;
        } else {
#pragma unroll
            for (int t = 0; t < 4; t++) {
                int sj = jb + t;
                candv[t] = ((unsigned)sj < (unsigned)WW) ? __ldg(s + si * WW + sj) : SENT;
            }
        }
    } else {
        int ws = jb & ~3;                         // aligned window start
        if (ws >= 0 && ws + 7 < WW) {
            uint4 n0 = __ldg(reinterpret_cast<const uint4*>(s + si * WW + ws));
            uint4 n1 = __ldg(reinterpret_cast<const uint4*>(s + si * WW + ws + 4));
            uint32_t w[8] = {n0.x, n0.y, n0.z, n0.w, n1.x, n1.y, n1.z, n1.w};
            int off = jb & 3;
#pragma unroll
            for (int t = 0; t < 4; t++) candv[t] = w[off + t];
        } else {
#pragma unroll
            for (int t = 0; t < 4; t++) {
                int sj = jb + t;
                candv[t] = ((unsigned)sj < (unsigned)WW) ? __ldg(s + si * WW + sj) : SENT;
            }
        }
    }
    uint32_t curv[4] = {cur.x, cur.y, cur.z, cur.w};
    uint32_t outv[4];
#pragma unroll
    for (int t = 0; t < 4; t++) outv[t] = jfa_better5(curv[t], candv[t], i, j0 + t);
    *reinterpret_cast<uint4*>(dpt + i * WW + j0) = make_uint4(outv[0], outv[1], outv[2], outv[3]);
}

// ---------------------------------------------------------------------------
// 4b) fused row-local pair (R5 champion body): (0,-k) then (0,+k), in place.
__global__ void __launch_bounds__(480) jfa_rowpair_kernel(int srcSel, int k) {
    __shared__ uint32_t row[WW];
    const int b = blockIdx.z;
    const int i = blockIdx.y;
    uint32_t* __restrict__ s = g_near[srcSel][b] + i * WW;
    const int j0 = threadIdx.x * 4;
    uint4 v = *reinterpret_cast<const uint4*>(s + j0);
    *reinterpret_cast<uint4*>(row + j0) = v;
    uint32_t curv[4] = {v.x, v.y, v.z, v.w};
    __syncthreads();

    // direction (0,-k): cand = row[j + k]
    uint32_t nv[4];
    {
        int jb = j0 + k;
        uint32_t candv[4];
        if ((k & 3) == 0) {
            if (jb + 3 < WW) {
                uint4 n = *reinterpret_cast<const uint4*>(row + jb);
                candv[0] = n.x; candv[1] = n.y; candv[2] = n.z; candv[3] = n.w;
            } else {
#pragma unroll
                for (int t = 0; t < 4; t++) candv[t] = (jb + t < WW) ? row[jb + t] : SENT;
            }
        } else {
            int ws = jb & ~3;
            if (ws + 7 < WW) {
                uint4 n0 = *reinterpret_cast<const uint4*>(row + ws);
                uint4 n1 = *reinterpret_cast<const uint4*>(row + ws + 4);
                uint32_t w[8] = {n0.x, n0.y, n0.z, n0.w, n1.x, n1.y, n1.z, n1.w};
                int off = jb & 3;
#pragma unroll
                for (int t = 0; t < 4; t++) candv[t] = w[off + t];
            } else {
#pragma unroll
                for (int t = 0; t < 4; t++) candv[t] = (jb + t < WW) ? row[jb + t] : SENT;
            }
        }
#pragma unroll
        for (int t = 0; t < 4; t++) nv[t] = jfa_better5(curv[t], candv[t], i, j0 + t);
    }
    __syncthreads();           // all reads of stage-0 done
    *reinterpret_cast<uint4*>(row + j0) = make_uint4(nv[0], nv[1], nv[2], nv[3]);
    __syncthreads();           // stage-1 row visible

    // direction (0,+k): cand = row[j - k]
    uint32_t ov[4];
    {
        int jb = j0 - k;
        uint32_t candv[4];
        if ((k & 3) == 0) {
            if (jb >= 0) {
                uint4 n = *reinterpret_cast<const uint4*>(row + jb);
                candv[0] = n.x; candv[1] = n.y; candv[2] = n.z; candv[3] = n.w;
            } else {
#pragma unroll
                for (int t = 0; t < 4; t++) candv[t] = (jb + t >= 0) ? row[jb + t] : SENT;
            }
        } else {
            int ws = jb & ~3;
            if (ws >= 0) {     // ws+7 < WW always holds here (jb+3 < WW)
                uint4 n0 = *reinterpret_cast<const uint4*>(row + ws);
                uint4 n1 = *reinterpret_cast<const uint4*>(row + ws + 4);
                uint32_t w[8] = {n0.x, n0.y, n0.z, n0.w, n1.x, n1.y, n1.z, n1.w};
                int off = jb & 3;
#pragma unroll
                for (int t = 0; t < 4; t++) candv[t] = w[off + t];
            } else {
#pragma unroll
                for (int t = 0; t < 4; t++) candv[t] = (jb + t >= 0) ? row[jb + t] : SENT;
            }
        }
#pragma unroll
        for (int t = 0; t < 4; t++) ov[t] = jfa_better5(nv[t], candv[t], i, j0 + t);
    }
    *reinterpret_cast<uint4*>(s + j0) = make_uint4(ov[0], ov[1], ov[2], ov[3]);
}

// ---------------------------------------------------------------------------
// 5) filled depth + distance map
__global__ void fill_kernel(int nb, int finalSel) {
    int t = blockIdx.x * blockDim.x + threadIdx.x;
    int total = nb * HH * WW;
    if (t >= total) return;
    int b = t / (HH * WW);
    int pix = t % (HH * WW);
    int i = pix / WW;
    int j = pix % WW;
    float dep = g_depth[b][pix];
    uint32_t nn = g_near[finalSel][b][pix];
    int nr = (int)(nn >> 16);     if (nr > HH - 1) nr = HH - 1;
    int nc = (int)(nn & 0xFFFFu); if (nc > WW - 1) nc = WW - 1;
    bool valid = (dep != 0.f);
    float filled = valid ? dep : g_depth[b][nr * WW + nc];
    float dr = __fadd_rn((float)i, -(float)nr);
    float dc = __fadd_rn((float)j, -(float)nc);
    float dist = valid ? 0.f : __fsqrt_rn(__fadd_rn(__fmul_rn(dr, dr), __fmul_rn(dc, dc)));
    g_full[b][0][pix] = filled;
    g_full[b][1][pix] = dist;
}

// ---------------------------------------------------------------------------
// 6) jax.image.resize(method='linear', antialias=True): separable triangle,
//    fp32 weights exactly as jax computes them, fp32 accumulation.
__global__ void resize_kernel(float* __restrict__ out, int nb) {
    int t = blockIdx.x * blockDim.x + threadIdx.x;
    int total = nb * 2 * OH * OW;
    if (t >= total) return;
    int ox = t % OW;
    int oy = (t / OW) % OH;
    int ch = (t / (OW * OH)) % 2;
    int b  =  t / (OW * OH * 2);

    const double s_h = (double)OH / (double)HH;
    const double s_w = (double)OW / (double)WW;
    const float inv_h = (float)(1.0 / s_h);
    const float inv_w = (float)(1.0 / s_w);

    float sfy = __fadd_rn(__fmul_rn(__fadd_rn((float)oy, 0.5f), inv_h), -0.5f);
    float sfx = __fadd_rn(__fmul_rn(__fadd_rn((float)ox, 0.5f), inv_w), -0.5f);

    int y0 = (int)ceilf(sfy - inv_h) - 1;  if (y0 < 0) y0 = 0;
    int y1 = (int)floorf(sfy + inv_h) + 1; if (y1 > HH - 1) y1 = HH - 1;
    int x0 = (int)ceilf(sfx - inv_w) - 1;  if (x0 < 0) x0 = 0;
    int x1 = (int)floorf(sfx + inv_w) + 1; if (x1 > WW - 1) x1 = WW - 1;

    float wx[10];
    float wxs = 0.0f;
    int nx = x1 - x0 + 1;
    if (nx > 10) nx = 10;
    for (int k = 0; k < nx; k++) {
        float d = fabsf(__fadd_rn(sfx, -(float)(x0 + k)));
        float xx = __fdiv_rn(d, inv_w);
        float w = __fadd_rn(1.0f, -xx);
        if (w < 0.0f) w = 0.0f;
        wx[k] = w;
        wxs = __fadd_rn(wxs, w);
    }
    for (int k = 0; k < nx; k++) wx[k] = __fdiv_rn(wx[k], wxs);

    const float* __restrict__ src = g_full[b][ch];
    float acc = 0.0f;
    float wys = 0.0f;
    float wy[10];
    int ny = y1 - y0 + 1;
    if (ny > 10) ny = 10;
    for (int k = 0; k < ny; k++) {
        float d = fabsf(__fadd_rn(sfy, -(float)(y0 + k)));
        float xx = __fdiv_rn(d, inv_h);
        float w = __fadd_rn(1.0f, -xx);
        if (w < 0.0f) w = 0.0f;
        wy[k] = w;
        wys = __fadd_rn(wys, w);
    }
    for (int k = 0; k < ny; k++) {
        float wyn = __fdiv_rn(wy[k], wys);
        const float* row = src + (y0 + k) * WW;
        float rowacc = 0.0f;
        for (int m = 0; m < nx; m++) {
            rowacc = __fmaf_rn(wx[m], row[x0 + m], rowacc);
        }
        acc = __fmaf_rn(wyn, rowacc, acc);
    }
    out[(((size_t)b * 2 + ch) * OH + oy) * OW + ox] = acc;
}

// ---------------------------------------------------------------------------
extern "C" void kernel_launch(void* const* d_in, const int* in_sizes, int n_in,
                              void* d_out, int out_size) {
    const float* pts  = (const float*)d_in[0];  // (B,N,3)
    const float* pose = (const float*)d_in[1];  // (B,4,4)
    const float* ext  = (const float*)d_in[2];  // (B,4,4)
    const float* intr = (const float*)d_in[3];  // (B,3,3)

    int nb = in_sizes[1] / 16;
    if (nb < 1) nb = 1;
    if (nb > BB) nb = BB;
    int N = in_sizes[0] / (nb * 3);

    int totalPix = nb * HH * WW;

    zero_depth_kernel<<<(totalPix / 4 + 255) / 256, 256>>>(nb);

    dim3 sg((N + 255) / 256, nb);
    scatter_kernel<<<sg, 256>>>(pts, pose, ext, intr, N);

    dim3 jg(1, HH, nb);
    int src;

    // step k=1 FIRST: seed init + A,B fused; then C, [D,E] rowpair, F, G, H.
    jfa_pair_init<<<jg, 480>>>(nb);                       // -> g_near[0]
    src = 0;
    jfa_pass_kernel<<<jg, 480>>>(src, -1,  1); src ^= 1;  // C
    jfa_rowpair_kernel<<<jg, 480>>>(src, 1);              // D,E in place
    jfa_pass_kernel<<<jg, 480>>>(src,  1, -1); src ^= 1;  // F
    jfa_pass_kernel<<<jg, 480>>>(src,  1,  0); src ^= 1;  // G
    jfa_pass_kernel<<<jg, 480>>>(src,  1,  1); src ^= 1;  // H

    // remaining steps: 1024, 512, 256, 128, 64, 32, 16, 8, 4, 2, 1
    static const int steps[11] = {1024, 512, 256, 128, 64, 32, 16, 8, 4, 2, 1};
    for (int s = 0; s < 11; s++) {
        int k = steps[s];
        jfa_pass_kernel<<<jg, 480>>>(src, -k, -k); src ^= 1;  // A
        jfa_pass_kernel<<<jg, 480>>>(src, -k,  0); src ^= 1;  // B
        jfa_pass_kernel<<<jg, 480>>>(src, -k,  k); src ^= 1;  // C
        jfa_rowpair_kernel<<<jg, 480>>>(src, k);              // D,E in place
        jfa_pass_kernel<<<jg, 480>>>(src,  k, -k); src ^= 1;  // F
        jfa_pass_kernel<<<jg, 480>>>(src,  k,  0); src ^= 1;  // G
        jfa_pass_kernel<<<jg, 480>>>(src,  k,  k); src ^= 1;  // H
    }

    fill_kernel<<<(totalPix + 255) / 256, 256>>>(nb, src);

    int outTotal = nb * 2 * OH * OW;
    resize_kernel<<<(outTotal + 255) / 256, 256>>>((float*)d_out, nb);
}

// round 17
// speedup vs baseline: 1.7365x; 1.0778x over previous
#include <cuda_runtime.h>
#include <stdint.h>
#include <math.h>

#define HH 1280
#define WW 1920
#define BB 2
#define OH 427
#define OW 640
#define SENT 0xFFFFFFFFu

// Scratch (device globals: allocation-free rule)
__device__ float    g_depth[BB][HH * WW];          // 19.6 MB
__device__ uint32_t g_near[2][BB][HH * WW];        // 2 x 19.6 MB, ping-pong
__device__ float    g_full[BB][2][HH * WW];        // filled + dist, 39.3 MB

// ---------------------------------------------------------------------------
// XLA fused-emitter dot: separate multiplies, k-ascending adds, NO fma.
__device__ __forceinline__ float dot3_nofma(float a0, float a1, float a2,
                                            float b0, float b1, float b2) {
    float p0 = __fmul_rn(a0, b0);
    float p1 = __fmul_rn(a1, b1);
    float p2 = __fmul_rn(a2, b2);
    return __fadd_rn(__fadd_rn(p0, p1), p2);
}

// R5-convention winner select: strict '<', exact int dist, SENT -> INT_MAX.
__device__ __forceinline__ uint32_t jfa_better5(uint32_t c0, uint32_t cand, int i, int j) {
    int db, dc;
    if (c0 == SENT) db = 0x7FFFFFFF;
    else { int a = i - (int)(c0 >> 16); int e = j - (int)(c0 & 0xFFFFu); db = a * a + e * e; }
    if (cand == SENT) dc = 0x7FFFFFFF;
    else { int a = i - (int)(cand >> 16); int e = j - (int)(cand & 0xFFFFu); dc = a * a + e * e; }
    return (dc < db) ? cand : c0;
}

__device__ __forceinline__ uint32_t seedv(int r, int c, float d) {
    return (d != 0.f) ? (uint32_t)((r << 16) | c) : SENT;
}

// ---------------------------------------------------------------------------
// 1) zero depth canvas
__global__ void zero_depth_kernel(int nb) {
    int t = blockIdx.x * blockDim.x + threadIdx.x;
    int total = nb * HH * WW / 4;
    if (t < total) reinterpret_cast<float4*>(g_depth)[t] = make_float4(0.f, 0.f, 0.f, 0.f);
}

// ---------------------------------------------------------------------------
// 2) project points, scatter-add depth (duplicates sum, like reference)
__global__ void scatter_kernel(const float* __restrict__ pts,
                               const float* __restrict__ pose,
                               const float* __restrict__ ext,
                               const float* __restrict__ intr,
                               int N) {
    int idx = blockIdx.x * blockDim.x + threadIdx.x;
    int b = blockIdx.y;
    if (idx >= N) return;
    const float* p = pts + ((size_t)b * N + idx) * 3;
    float x = p[0], y = p[1], z = p[2];
    const float* P = pose + b * 16;
    const float* E = ext + b * 16;
    const float* K = intr + b * 9;
    float wx = __fadd_rn(dot3_nofma(x, y, z, P[0], P[1], P[2]),  P[3]);
    float wy = __fadd_rn(dot3_nofma(x, y, z, P[4], P[5], P[6]),  P[7]);
    float wz = __fadd_rn(dot3_nofma(x, y, z, P[8], P[9], P[10]), P[11]);
    float cx = __fadd_rn(dot3_nofma(wx, wy, wz, E[0], E[1], E[2]),  E[3]);
    float cy = __fadd_rn(dot3_nofma(wx, wy, wz, E[4], E[5], E[6]),  E[7]);
    float cz = __fadd_rn(dot3_nofma(wx, wy, wz, E[8], E[9], E[10]), E[11]);
    float pu = dot3_nofma(cx, cy, cz, K[0], K[1], K[2]);
    float pv = dot3_nofma(cx, cy, cz, K[3], K[4], K[5]);
    float pw = dot3_nofma(cx, cy, cz, K[6], K[7], K[8]);
    float u = __fdiv_rn(pu, pw);
    float v = __fdiv_rn(pv, pw);
    int r = (int)floorf(v);
    int c = (int)floorf(u);
    if (r >= 0 && r < HH && c >= 0 && c < WW) {
        float x2 = __fmul_rn(x, x);
        float y2 = __fmul_rn(y, y);
        float z2 = __fmul_rn(z, z);
        float d = __fsqrt_rn(__fadd_rn(__fadd_rn(x2, y2), z2));
        atomicAdd(&g_depth[b][r * WW + c], d);
    }
}

// ---------------------------------------------------------------------------
// 3) first JFA op: fused seed-init + directions A=(-1,-1), B=(-1,0) of the
//    k=1 step. Seeds formed inline from depth (replaces init_near kernel).
__global__ void __launch_bounds__(480) jfa_pair_init(int nb) {
    const int b = blockIdx.z;
    const int i = blockIdx.y;
    const int j0 = threadIdx.x * 4;
    const float* __restrict__ dp = g_depth[b];
    uint32_t* __restrict__ dst = g_near[0][b];

    const int r1 = i + 1, r2 = i + 2;
    const bool ok1 = (r1 < HH);
    const bool ok2 = (r2 < HH);
    const bool okr = (j0 + 7 < WW);

    float4 dC = *reinterpret_cast<const float4*>(dp + i * WW + j0);
    uint32_t curv[4] = { seedv(i, j0 + 0, dC.x), seedv(i, j0 + 1, dC.y),
                         seedv(i, j0 + 2, dC.z), seedv(i, j0 + 3, dC.w) };

    uint32_t w1[8], w2[8];
#pragma unroll
    for (int t = 0; t < 8; t++) { w1[t] = SENT; w2[t] = SENT; }
    if (ok1) {
        float4 a = __ldg(reinterpret_cast<const float4*>(dp + r1 * WW + j0));
        w1[0] = seedv(r1, j0 + 0, a.x); w1[1] = seedv(r1, j0 + 1, a.y);
        w1[2] = seedv(r1, j0 + 2, a.z); w1[3] = seedv(r1, j0 + 3, a.w);
        if (okr) {
            float4 c = __ldg(reinterpret_cast<const float4*>(dp + r1 * WW + j0 + 4));
            w1[4] = seedv(r1, j0 + 4, c.x); w1[5] = seedv(r1, j0 + 5, c.y);
            w1[6] = seedv(r1, j0 + 6, c.z); w1[7] = seedv(r1, j0 + 7, c.w);
        }
    }
    if (ok2) {
        float4 a = __ldg(reinterpret_cast<const float4*>(dp + r2 * WW + j0));
        w2[0] = seedv(r2, j0 + 0, a.x); w2[1] = seedv(r2, j0 + 1, a.y);
        w2[2] = seedv(r2, j0 + 2, a.z); w2[3] = seedv(r2, j0 + 3, a.w);
        if (okr) {
            float4 c = __ldg(reinterpret_cast<const float4*>(dp + r2 * WW + j0 + 4));
            w2[4] = seedv(r2, j0 + 4, c.x); w2[5] = seedv(r2, j0 + 5, c.y);
            w2[6] = seedv(r2, j0 + 6, c.z); w2[7] = seedv(r2, j0 + 7, c.w);
        }
    }

    uint32_t outv[4];
#pragma unroll
    for (int t = 0; t < 4; t++) {
        int j = j0 + t;
        uint32_t a1 = jfa_better5(curv[t], w1[t + 1], i, j);    // post-A
        uint32_t a2 = jfa_better5(w1[t], w2[t + 1], r1, j);     // candB
        outv[t] = jfa_better5(a1, a2, i, j);                    // post-B
    }
    *reinterpret_cast<uint4*>(dst + i * WW + j0) = make_uint4(outv[0], outv[1], outv[2], outv[3]);
}

// ---------------------------------------------------------------------------
// 4) one JFA direction pass (champion body).
__global__ void __launch_bounds__(480) jfa_pass_kernel(int srcSel, int dy, int dx) {
    const int b = blockIdx.z;
    const int i = blockIdx.y;
    const int j0 = threadIdx.x * 4;
    const uint32_t* __restrict__ s = g_near[srcSel][b];
    uint32_t* __restrict__ dpt = g_near[srcSel ^ 1][b];
    uint4 cur = *reinterpret_cast<const uint4*>(s + i * WW + j0);
    const int si = i - dy;
    const bool rowok = ((unsigned)si < (unsigned)HH);
    uint32_t candv[4];
    const int jb = j0 - dx;                       // first source column
    if (!rowok) {
        candv[0] = candv[1] = candv[2] = candv[3] = SENT;
    } else if ((dx & 3) == 0) {
        if (jb >= 0 && jb + 3 < WW) {
            uint4 n = __ldg(reinterpret_cast<const uint4*>(s + si * WW + jb));
            candv[0] = n.x; candv[1] = n.y; candv[2] = n.z; candv[3] = n.w;
        } else {
#pragma unroll
            for (int t = 0; t < 4; t++) {
                int sj = jb + t;
                candv[t] = ((unsigned)sj < (unsigned)WW) ? __ldg(s + si * WW + sj) : SENT;
            }
        }
    } else {
        int ws = jb & ~3;                         // aligned window start
        if (ws >= 0 && ws + 7 < WW) {
            uint4 n0 = __ldg(reinterpret_cast<const uint4*>(s + si * WW + ws));
            uint4 n1 = __ldg(reinterpret_cast<const uint4*>(s + si * WW + ws + 4));
            uint32_t w[8] = {n0.x, n0.y, n0.z, n0.w, n1.x, n1.y, n1.z, n1.w};
            int off = jb & 3;
#pragma unroll
            for (int t = 0; t < 4; t++) candv[t] = w[off + t];
        } else {
#pragma unroll
            for (int t = 0; t < 4; t++) {
                int sj = jb + t;
                candv[t] = ((unsigned)sj < (unsigned)WW) ? __ldg(s + si * WW + sj) : SENT;
            }
        }
    }
    uint32_t curv[4] = {cur.x, cur.y, cur.z, cur.w};
    uint32_t outv[4];
#pragma unroll
    for (int t = 0; t < 4; t++) outv[t] = jfa_better5(curv[t], candv[t], i, j0 + t);
    *reinterpret_cast<uint4*>(dpt + i * WW + j0) = make_uint4(outv[0], outv[1], outv[2], outv[3]);
}

// ---------------------------------------------------------------------------
// 5) fused C,D,E: directions C=(-k,+k) [cand = src(i+k, j-k), gmem Jacobi on
//    pre-C buffer], then D=(0,-k), E=(0,+k) row-local on the post-C row in
//    smem. Reads src, writes dst (one flip). Validated bit-exact (R13).
__global__ void __launch_bounds__(480) jfa_cde_kernel(int srcSel, int k) {
    __shared__ uint32_t row[WW];
    const int b = blockIdx.z;
    const int i = blockIdx.y;
    const int j0 = threadIdx.x * 4;
    const uint32_t* __restrict__ src = g_near[srcSel][b];
    uint32_t* __restrict__ dst = g_near[srcSel ^ 1][b];
    uint4 v = *reinterpret_cast<const uint4*>(src + i * WW + j0);
    uint32_t cur[4] = {v.x, v.y, v.z, v.w};

    // C = (-k, +k): cand(i,j) = src(i+k, j-k)
    uint32_t cC[4];
    {
        const int si = i + k;
        const int jb = j0 - k;
        if ((unsigned)si < (unsigned)HH) {
            const uint32_t* rp = src + si * WW;
            if ((k & 3) == 0) {   // aligned: all-or-none window
                const bool ok = ((unsigned)jb < (unsigned)WW);
                uint4 n = __ldg(reinterpret_cast<const uint4*>(rp + (ok ? jb : 0)));
                if (!ok) { n.x = SENT; n.y = SENT; n.z = SENT; n.w = SENT; }
                cC[0] = n.x; cC[1] = n.y; cC[2] = n.z; cC[3] = n.w;
            } else {
#pragma unroll
                for (int t = 0; t < 4; t++) {
                    int sj = jb + t;
                    cC[t] = ((unsigned)sj < (unsigned)WW) ? __ldg(rp + sj) : SENT;
                }
            }
        } else {
            cC[0] = cC[1] = cC[2] = cC[3] = SENT;
        }
    }
    uint32_t v0[4];
#pragma unroll
    for (int t = 0; t < 4; t++) v0[t] = jfa_better5(cur[t], cC[t], i, j0 + t);
    *reinterpret_cast<uint4*>(row + j0) = make_uint4(v0[0], v0[1], v0[2], v0[3]);
    __syncthreads();

    // D = (0, -k): cand = row[j + k]   (post-C)
    uint32_t v1[4];
    {
        const int jd = j0 + k;
        uint32_t cD[4];
        if ((k & 3) == 0 && jd + 3 < WW) {
            uint4 n = *reinterpret_cast<const uint4*>(row + jd);
            cD[0] = n.x; cD[1] = n.y; cD[2] = n.z; cD[3] = n.w;
        } else {
#pragma unroll
            for (int t = 0; t < 4; t++) cD[t] = (jd + t < WW) ? row[jd + t] : SENT;
        }
#pragma unroll
        for (int t = 0; t < 4; t++) v1[t] = jfa_better5(v0[t], cD[t], i, j0 + t);
    }
    __syncthreads();        // all D reads of post-C row done
    *reinterpret_cast<uint4*>(row + j0) = make_uint4(v1[0], v1[1], v1[2], v1[3]);
    __syncthreads();        // post-D row visible

    // E = (0, +k): cand = row[j - k]   (post-D)
    uint32_t outv[4];
    {
        const int je = j0 - k;
        uint32_t cE[4];
        if ((k & 3) == 0 && je >= 0) {
            uint4 n = *reinterpret_cast<const uint4*>(row + je);
            cE[0] = n.x; cE[1] = n.y; cE[2] = n.z; cE[3] = n.w;
        } else {
#pragma unroll
            for (int t = 0; t < 4; t++) cE[t] = (je + t >= 0) ? row[je + t] : SENT;
        }
#pragma unroll
        for (int t = 0; t < 4; t++) outv[t] = jfa_better5(v1[t], cE[t], i, j0 + t);
    }
    *reinterpret_cast<uint4*>(dst + i * WW + j0) = make_uint4(outv[0], outv[1], outv[2], outv[3]);
}

// ---------------------------------------------------------------------------
// 6) filled depth + distance map
__global__ void fill_kernel(int nb, int finalSel) {
    int t = blockIdx.x * blockDim.x + threadIdx.x;
    int total = nb * HH * WW;
    if (t >= total) return;
    int b = t / (HH * WW);
    int pix = t % (HH * WW);
    int i = pix / WW;
    int j = pix % WW;
    float dep = g_depth[b][pix];
    uint32_t nn = g_near[finalSel][b][pix];
    int nr = (int)(nn >> 16);     if (nr > HH - 1) nr = HH - 1;
    int nc = (int)(nn & 0xFFFFu); if (nc > WW - 1) nc = WW - 1;
    bool valid = (dep != 0.f);
    float filled = valid ? dep : g_depth[b][nr * WW + nc];
    float dr = __fadd_rn((float)i, -(float)nr);
    float dc = __fadd_rn((float)j, -(float)nc);
    float dist = valid ? 0.f : __fsqrt_rn(__fadd_rn(__fmul_rn(dr, dr), __fmul_rn(dc, dc)));
    g_full[b][0][pix] = filled;
    g_full[b][1][pix] = dist;
}

// ---------------------------------------------------------------------------
// 7) jax.image.resize(method='linear', antialias=True): separable triangle,
//    fp32 weights exactly as jax computes them, fp32 accumulation.
__global__ void resize_kernel(float* __restrict__ out, int nb) {
    int t = blockIdx.x * blockDim.x + threadIdx.x;
    int total = nb * 2 * OH * OW;
    if (t >= total) return;
    int ox = t % OW;
    int oy = (t / OW) % OH;
    int ch = (t / (OW * OH)) % 2;
    int b  =  t / (OW * OH * 2);

    const double s_h = (double)OH / (double)HH;
    const double s_w = (double)OW / (double)WW;
    const float inv_h = (float)(1.0 / s_h);
    const float inv_w = (float)(1.0 / s_w);

    float sfy = __fadd_rn(__fmul_rn(__fadd_rn((float)oy, 0.5f), inv_h), -0.5f);
    float sfx = __fadd_rn(__fmul_rn(__fadd_rn((float)ox, 0.5f), inv_w), -0.5f);

    int y0 = (int)ceilf(sfy - inv_h) - 1;  if (y0 < 0) y0 = 0;
    int y1 = (int)floorf(sfy + inv_h) + 1; if (y1 > HH - 1) y1 = HH - 1;
    int x0 = (int)ceilf(sfx - inv_w) - 1;  if (x0 < 0) x0 = 0;
    int x1 = (int)floorf(sfx + inv_w) + 1; if (x1 > WW - 1) x1 = WW - 1;

    float wx[10];
    float wxs = 0.0f;
    int nx = x1 - x0 + 1;
    if (nx > 10) nx = 10;
    for (int k = 0; k < nx; k++) {
        float d = fabsf(__fadd_rn(sfx, -(float)(x0 + k)));
        float xx = __fdiv_rn(d, inv_w);
        float w = __fadd_rn(1.0f, -xx);
        if (w < 0.0f) w = 0.0f;
        wx[k] = w;
        wxs = __fadd_rn(wxs, w);
    }
    for (int k = 0; k < nx; k++) wx[k] = __fdiv_rn(wx[k], wxs);

    const float* __restrict__ src = g_full[b][ch];
    float acc = 0.0f;
    float wys = 0.0f;
    float wy[10];
    int ny = y1 - y0 + 1;
    if (ny > 10) ny = 10;
    for (int k = 0; k < ny; k++) {
        float d = fabsf(__fadd_rn(sfy, -(float)(y0 + k)));
        float xx = __fdiv_rn(d, inv_h);
        float w = __fadd_rn(1.0f, -xx);
        if (w < 0.0f) w = 0.0f;
        wy[k] = w;
        wys = __fadd_rn(wys, w);
    }
    for (int k = 0; k < ny; k++) {
        float wyn = __fdiv_rn(wy[k], wys);
        const float* row = src + (y0 + k) * WW;
        float rowacc = 0.0f;
        for (int m = 0; m < nx; m++) {
            rowacc = __fmaf_rn(wx[m], row[x0 + m], rowacc);
        }
        acc = __fmaf_rn(wyn, rowacc, acc);
    }
    out[(((size_t)b * 2 + ch) * OH + oy) * OW + ox] = acc;
}

// ---------------------------------------------------------------------------
extern "C" void kernel_launch(void* const* d_in, const int* in_sizes, int n_in,
                              void* d_out, int out_size) {
    const float* pts  = (const float*)d_in[0];  // (B,N,3)
    const float* pose = (const float*)d_in[1];  // (B,4,4)
    const float* ext  = (const float*)d_in[2];  // (B,4,4)
    const float* intr = (const float*)d_in[3];  // (B,3,3)

    int nb = in_sizes[1] / 16;
    if (nb < 1) nb = 1;
    if (nb > BB) nb = BB;
    int N = in_sizes[0] / (nb * 3);

    int totalPix = nb * HH * WW;

    zero_depth_kernel<<<(totalPix / 4 + 255) / 256, 256>>>(nb);

    dim3 sg((N + 255) / 256, nb);
    scatter_kernel<<<sg, 256>>>(pts, pose, ext, intr, N);

    dim3 jg(1, HH, nb);
    int src;

    // step k=1 FIRST: seed init + A,B fused; then [C,D,E] fused, F, G, H.
    jfa_pair_init<<<jg, 480>>>(nb);                       // -> g_near[0]
    src = 0;
    jfa_cde_kernel<<<jg, 480>>>(src, 1);       src ^= 1;  // C,D,E
    jfa_pass_kernel<<<jg, 480>>>(src,  1, -1); src ^= 1;  // F
    jfa_pass_kernel<<<jg, 480>>>(src,  1,  0); src ^= 1;  // G
    jfa_pass_kernel<<<jg, 480>>>(src,  1,  1); src ^= 1;  // H

    // remaining steps: 1024, 512, 256, 128, 64, 32, 16, 8, 4, 2, 1
    static const int steps[11] = {1024, 512, 256, 128, 64, 32, 16, 8, 4, 2, 1};
    for (int s = 0; s < 11; s++) {
        int k = steps[s];
        jfa_pass_kernel<<<jg, 480>>>(src, -k, -k); src ^= 1;  // A
        jfa_pass_kernel<<<jg, 480>>>(src, -k,  0); src ^= 1;  // B
        jfa_cde_kernel<<<jg, 480>>>(src, k);       src ^= 1;  // C,D,E
        jfa_pass_kernel<<<jg, 480>>>(src,  k, -k); src ^= 1;  // F
        jfa_pass_kernel<<<jg, 480>>>(src,  k,  0); src ^= 1;  // G
        jfa_pass_kernel<<<jg, 480>>>(src,  k,  k); src ^= 1;  // H
    }

    fill_kernel<<<(totalPix + 255) / 256, 256>>>(nb, src);

    int outTotal = nb * 2 * OH * OW;
    resize_kernel<<<(outTotal + 255) / 256, 256>>>((float*)d_out, nb);
}